// round 3
// baseline (speedup 1.0000x reference)
#include <cuda_runtime.h>
#include <math.h>

#define N_NODES 50000
#define N_EDGES 800000
#define IN_CH   64
#define HID     128

// ---------------- scratch (static device globals; no allocation) ----------------
__device__ int   g_cnt[N_NODES];
__device__ int   g_off[N_NODES];
__device__ int   g_cur[N_NODES];
__device__ int   g_bsum[256];
__device__ int   g_csr[N_EDGES];                        // src node id per CSR slot (keyed by dst)
__device__ __align__(16) float g_h[N_NODES * HID];      // hidden activations between layers
__device__ __align__(16) float g_mean[N_NODES * HID];   // mean-aggregated neighbor features
__device__ __align__(16) float g_out[N_NODES * HID];    // pre-normalization layer output
__device__ __align__(16) float g_W0[(2 * IN_CH) * HID]; // [K=128][128] k-major: rows 0..63 = Wl0^T, 64..127 = Wr0^T
__device__ __align__(16) float g_W1[(2 * HID) * HID];   // [K=256][128]
__device__ __align__(16) float g_W2[(2 * HID) * HID];

// ---------------- CSR build ----------------
__global__ void k_zero_cnt() {
    int i = blockIdx.x * blockDim.x + threadIdx.x;
    if (i < N_NODES) g_cnt[i] = 0;
}

// edge_index is int32 on the wire (JAX x64 disabled downgrades int64 -> int32).
__global__ void k_count(const int* __restrict__ ei) {
    int e = blockIdx.x * blockDim.x + threadIdx.x;
    if (e < N_EDGES) {
        int dst = ei[N_EDGES + e];
        if ((unsigned)dst < (unsigned)N_NODES)
            atomicAdd(&g_cnt[dst], 1);
    }
}

__global__ void k_scan1() {
    __shared__ int s[256];
    int i = blockIdx.x * 256 + threadIdx.x;
    int v = (i < N_NODES) ? g_cnt[i] : 0;
    s[threadIdx.x] = v;
    __syncthreads();
    for (int off = 1; off < 256; off <<= 1) {
        int t = (threadIdx.x >= off) ? s[threadIdx.x - off] : 0;
        __syncthreads();
        s[threadIdx.x] += t;
        __syncthreads();
    }
    if (i < N_NODES) g_off[i] = s[threadIdx.x] - v;   // exclusive within block
    if (threadIdx.x == 255) g_bsum[blockIdx.x] = s[255];
}

__global__ void k_scan2(int nb) {
    __shared__ int s[256];
    int v = (threadIdx.x < nb) ? g_bsum[threadIdx.x] : 0;
    s[threadIdx.x] = v;
    __syncthreads();
    for (int off = 1; off < 256; off <<= 1) {
        int t = (threadIdx.x >= off) ? s[threadIdx.x - off] : 0;
        __syncthreads();
        s[threadIdx.x] += t;
        __syncthreads();
    }
    g_bsum[threadIdx.x] = s[threadIdx.x] - v;         // exclusive block offsets
}

__global__ void k_scan3() {
    int i = blockIdx.x * blockDim.x + threadIdx.x;
    if (i < N_NODES) {
        int o = g_off[i] + g_bsum[i >> 8];
        g_off[i] = o;
        g_cur[i] = o;
    }
}

__global__ void k_fill(const int* __restrict__ ei) {
    int e = blockIdx.x * blockDim.x + threadIdx.x;
    if (e < N_EDGES) {
        int src = ei[e];
        int dst = ei[N_EDGES + e];
        if ((unsigned)dst < (unsigned)N_NODES && (unsigned)src < (unsigned)N_NODES) {
            int pos = atomicAdd(&g_cur[dst], 1);
            if ((unsigned)pos < (unsigned)N_EDGES) g_csr[pos] = src;
        }
    }
}

// ---------------- weight transpose+concat: Wcat[k][f] ----------------
// rows [0,DIN): Wl^T ; rows [DIN,2DIN): Wr^T
__global__ void k_wcat(const float* __restrict__ Wl, const float* __restrict__ Wr,
                       int DIN, int layer) {
    float* dst = (layer == 0) ? g_W0 : (layer == 1) ? g_W1 : g_W2;
    int i = blockIdx.x * blockDim.x + threadIdx.x;
    int total = 2 * DIN * HID;
    if (i < total) {
        int k = i >> 7;       // /128
        int f = i & 127;
        dst[i] = (k < DIN) ? Wl[f * DIN + k] : Wr[f * DIN + (k - DIN)];
    }
}

// ---------------- mean aggregation: warp per dst node ----------------
__global__ void k_agg(const float* __restrict__ xin, int use_h, int d) {
    const float* __restrict__ h = use_h ? g_h : xin;
    int gw   = (blockIdx.x * blockDim.x + threadIdx.x) >> 5;
    int lane = threadIdx.x & 31;
    if (gw >= N_NODES) return;
    int start = g_off[gw];
    int cnt   = g_cnt[gw];
    float a0 = 0.f, a1 = 0.f, a2 = 0.f, a3 = 0.f;
    if (d == 128) {
        for (int e = 0; e < cnt; e++) {
            const float* hp = h + (size_t)g_csr[start + e] * 128;
            a0 += hp[lane];      a1 += hp[lane + 32];
            a2 += hp[lane + 64]; a3 += hp[lane + 96];
        }
    } else {  // d == 64
        for (int e = 0; e < cnt; e++) {
            const float* hp = h + (size_t)g_csr[start + e] * 64;
            a0 += hp[lane];      a1 += hp[lane + 32];
        }
    }
    float inv = 1.f / fmaxf((float)cnt, 1.f);
    float* mp = g_mean + (size_t)gw * d;
    mp[lane]      = a0 * inv;
    mp[lane + 32] = a1 * inv;
    if (d == 128) {
        mp[lane + 64] = a2 * inv;
        mp[lane + 96] = a3 * inv;
    }
}

// ---------------- transform: out = mean@Wl^T + bias + x@Wr^T ----------------
// Block: 256 threads, tile 64 nodes x 128 outputs. Per thread: 4 nodes x 8 outs.
// K = 2*DIN virtual reduction dim: first DIN rows use g_mean, rest use A2.
__global__ __launch_bounds__(256) void k_transform(
    const float* __restrict__ xin, int use_h, int layer,
    const float* __restrict__ bias, int DIN)
{
    const float* __restrict__ A1 = g_mean;
    const float* __restrict__ A2 = use_h ? g_h : xin;
    const float* __restrict__ Wcat = (layer == 0) ? g_W0 : (layer == 1) ? g_W1 : g_W2;

    __shared__ __align__(16) float As[32 * 65];  // [kk][n], pad 65 -> conflict-free transposed stores
    __shared__ __align__(16) float Ws[32 * 128]; // [kk][f]

    const int tid   = threadIdx.x;
    const int tx    = tid & 15;         // f group
    const int ty    = tid >> 4;         // node group
    const int f0    = tx * 8;
    const int nl0   = ty * 4;
    const int node0 = blockIdx.x * 64;

    float acc[4][8];
#pragma unroll
    for (int i = 0; i < 4; i++)
#pragma unroll
        for (int j = 0; j < 8; j++) acc[i][j] = 0.f;

    const int K = 2 * DIN;
    // loader indices
    const int lkk = tid & 31;           // k within chunk (A loader)
    const int lng = tid >> 5;           // 0..7      (A loader node group)
    const int lf  = tid & 127;          // f         (W loader)
    const int lkg = tid >> 7;           // 0..1      (W loader k group)

    for (int c0 = 0; c0 < K; c0 += 32) {
        // chunk never straddles the A1/A2 boundary (DIN multiple of 32)
        const float* Asrc = (c0 < DIN) ? A1 : A2;
        const int cb = (c0 < DIN) ? c0 : (c0 - DIN);
#pragma unroll
        for (int r = 0; r < 8; r++) {
            int n = lng * 8 + r;
            int node = node0 + n;
            float v = 0.f;
            if (node < N_NODES) v = Asrc[(size_t)node * DIN + cb + lkk];
            As[lkk * 65 + n] = v;
        }
#pragma unroll
        for (int r = 0; r < 16; r++) {
            int kk = lkg * 16 + r;
            Ws[kk * 128 + lf] = Wcat[(size_t)(c0 + kk) * 128 + lf];
        }
        __syncthreads();

#pragma unroll
        for (int kk = 0; kk < 32; kk++) {
            float a0 = As[kk * 65 + nl0 + 0];
            float a1 = As[kk * 65 + nl0 + 1];
            float a2 = As[kk * 65 + nl0 + 2];
            float a3 = As[kk * 65 + nl0 + 3];
            float4 w0 = *(const float4*)&Ws[kk * 128 + f0];
            float4 w1 = *(const float4*)&Ws[kk * 128 + f0 + 4];
            float w[8] = {w0.x, w0.y, w0.z, w0.w, w1.x, w1.y, w1.z, w1.w};
#pragma unroll
            for (int j = 0; j < 8; j++) {
                acc[0][j] += a0 * w[j];
                acc[1][j] += a1 * w[j];
                acc[2][j] += a2 * w[j];
                acc[3][j] += a3 * w[j];
            }
        }
        __syncthreads();
    }

    float bs[8];
#pragma unroll
    for (int j = 0; j < 8; j++) bs[j] = bias[f0 + j];

#pragma unroll
    for (int i = 0; i < 4; i++) {
        int node = node0 + nl0 + i;
        if (node < N_NODES) {
            float4 o0 = make_float4(acc[i][0] + bs[0], acc[i][1] + bs[1],
                                    acc[i][2] + bs[2], acc[i][3] + bs[3]);
            float4 o1 = make_float4(acc[i][4] + bs[4], acc[i][5] + bs[5],
                                    acc[i][6] + bs[6], acc[i][7] + bs[7]);
            *(float4*)&g_out[(size_t)node * 128 + f0]     = o0;
            *(float4*)&g_out[(size_t)node * 128 + f0 + 4] = o1;
        }
    }
}

// ---------------- L2 normalize (+optional relu): warp per node ----------------
__global__ void k_norm(float* __restrict__ dout, int to_out, int relu) {
    int gw   = (blockIdx.x * blockDim.x + threadIdx.x) >> 5;
    int lane = threadIdx.x & 31;
    if (gw >= N_NODES) return;
    const float* ip = g_out + (size_t)gw * 128;
    float v0 = ip[lane], v1 = ip[lane + 32], v2 = ip[lane + 64], v3 = ip[lane + 96];
    float ss = v0 * v0 + v1 * v1 + v2 * v2 + v3 * v3;
#pragma unroll
    for (int m = 16; m; m >>= 1) ss += __shfl_xor_sync(0xffffffffu, ss, m);
    float scale = 1.f / fmaxf(sqrtf(ss), 1e-12f);
    v0 *= scale; v1 *= scale; v2 *= scale; v3 *= scale;
    if (relu) {
        v0 = fmaxf(v0, 0.f); v1 = fmaxf(v1, 0.f);
        v2 = fmaxf(v2, 0.f); v3 = fmaxf(v3, 0.f);
    }
    float* op = (to_out ? dout : g_h) + (size_t)gw * 128;
    op[lane] = v0; op[lane + 32] = v1; op[lane + 64] = v2; op[lane + 96] = v3;
}

// ---------------- launch ----------------
extern "C" void kernel_launch(void* const* d_in, const int* in_sizes, int n_in,
                              void* d_out, int out_size) {
    const float* x   = (const float*)d_in[0];
    const int*   ei  = (const int*)d_in[1];     // int32: JAX x64-disabled downgrades int64
    const float* Wl0 = (const float*)d_in[2];
    const float* bl0 = (const float*)d_in[3];
    const float* Wr0 = (const float*)d_in[4];
    const float* Wl1 = (const float*)d_in[5];
    const float* bl1 = (const float*)d_in[6];
    const float* Wr1 = (const float*)d_in[7];
    const float* Wl2 = (const float*)d_in[8];
    const float* bl2 = (const float*)d_in[9];
    const float* Wr2 = (const float*)d_in[10];
    float* out = (float*)d_out;

    const int NB_NODE  = (N_NODES + 255) / 256;          // 196
    const int NB_EDGE  = (N_EDGES + 255) / 256;          // 3125
    const int NB_WARP  = (N_NODES + 7) / 8;              // 6250 (warp/node, 256 thr)
    const int NB_TRANS = (N_NODES + 63) / 64;            // 782

    // CSR build
    k_zero_cnt<<<NB_NODE, 256>>>();
    k_count<<<NB_EDGE, 256>>>(ei);
    k_scan1<<<NB_NODE, 256>>>();
    k_scan2<<<1, 256>>>(NB_NODE);
    k_scan3<<<NB_NODE, 256>>>();
    k_fill<<<NB_EDGE, 256>>>(ei);

    // weight prep
    k_wcat<<<(2 * IN_CH * HID + 255) / 256, 256>>>(Wl0, Wr0, IN_CH, 0);
    k_wcat<<<(2 * HID * HID + 255) / 256, 256>>>(Wl1, Wr1, HID, 1);
    k_wcat<<<(2 * HID * HID + 255) / 256, 256>>>(Wl2, Wr2, HID, 2);

    // layer 0: x (d=64) -> g_h
    k_agg<<<NB_WARP, 256>>>(x, 0, IN_CH);
    k_transform<<<NB_TRANS, 256>>>(x, 0, 0, bl0, IN_CH);
    k_norm<<<NB_WARP, 256>>>(out, 0, 1);

    // layer 1: g_h (d=128) -> g_h
    k_agg<<<NB_WARP, 256>>>(x, 1, HID);
    k_transform<<<NB_TRANS, 256>>>(x, 1, 1, bl1, HID);
    k_norm<<<NB_WARP, 256>>>(out, 0, 1);

    // layer 2: g_h (d=128) -> out (no relu)
    k_agg<<<NB_WARP, 256>>>(x, 1, HID);
    k_transform<<<NB_TRANS, 256>>>(x, 1, 2, bl2, HID);
    k_norm<<<NB_WARP, 256>>>(out, 1, 0);
}

// round 4
// speedup vs baseline: 1.4364x; 1.4364x over previous
#include <cuda_runtime.h>
#include <math.h>

#define N_NODES 50000
#define N_EDGES 800000
#define IN_CH   64
#define HID     128

// ---------------- scratch (static device globals; no allocation) ----------------
__device__ int   g_cnt[N_NODES];
__device__ int   g_off[N_NODES];
__device__ int   g_cur[N_NODES];
__device__ int   g_bsum[256];
__device__ int   g_csr[N_EDGES];                        // src node id per CSR slot (keyed by dst)
__device__ __align__(16) float g_h[N_NODES * HID];      // hidden activations between layers
__device__ __align__(16) float g_mean[N_NODES * HID];   // mean-aggregated neighbor features
__device__ __align__(16) float g_W0[(2 * IN_CH) * HID]; // [K][128] k-major: Wl^T rows then Wr^T rows
__device__ __align__(16) float g_W1[(2 * HID) * HID];
__device__ __align__(16) float g_W2[(2 * HID) * HID];

// ---------------- packed f32x2 helpers ----------------
__device__ __forceinline__ unsigned long long pack2(float w) {
    unsigned long long r;
    unsigned u = __float_as_uint(w);
    asm("mov.b64 %0, {%1, %1};" : "=l"(r) : "r"(u));
    return r;
}
__device__ __forceinline__ void ffma2(unsigned long long& acc,
                                      unsigned long long a, unsigned long long b) {
    asm("fma.rn.f32x2 %0, %1, %2, %0;" : "+l"(acc) : "l"(a), "l"(b));
}

// ---------------- CSR build ----------------
__global__ void k_zero_cnt() {
    int i = blockIdx.x * blockDim.x + threadIdx.x;
    if (i < N_NODES) g_cnt[i] = 0;
}

// edge_index is int32 on the wire (JAX x64 disabled downgrades int64 -> int32).
__global__ void k_count(const int* __restrict__ ei) {
    int e = blockIdx.x * blockDim.x + threadIdx.x;
    if (e < N_EDGES) {
        int dst = ei[N_EDGES + e];
        if ((unsigned)dst < (unsigned)N_NODES)
            atomicAdd(&g_cnt[dst], 1);
    }
}

__global__ void k_scan1() {
    __shared__ int s[256];
    int i = blockIdx.x * 256 + threadIdx.x;
    int v = (i < N_NODES) ? g_cnt[i] : 0;
    s[threadIdx.x] = v;
    __syncthreads();
    for (int off = 1; off < 256; off <<= 1) {
        int t = (threadIdx.x >= off) ? s[threadIdx.x - off] : 0;
        __syncthreads();
        s[threadIdx.x] += t;
        __syncthreads();
    }
    if (i < N_NODES) g_off[i] = s[threadIdx.x] - v;
    if (threadIdx.x == 255) g_bsum[blockIdx.x] = s[255];
}

__global__ void k_scan2(int nb) {
    __shared__ int s[256];
    int v = (threadIdx.x < nb) ? g_bsum[threadIdx.x] : 0;
    s[threadIdx.x] = v;
    __syncthreads();
    for (int off = 1; off < 256; off <<= 1) {
        int t = (threadIdx.x >= off) ? s[threadIdx.x - off] : 0;
        __syncthreads();
        s[threadIdx.x] += t;
        __syncthreads();
    }
    g_bsum[threadIdx.x] = s[threadIdx.x] - v;
}

__global__ void k_scan3() {
    int i = blockIdx.x * blockDim.x + threadIdx.x;
    if (i < N_NODES) {
        int o = g_off[i] + g_bsum[i >> 8];
        g_off[i] = o;
        g_cur[i] = o;
    }
}

__global__ void k_fill(const int* __restrict__ ei) {
    int e = blockIdx.x * blockDim.x + threadIdx.x;
    if (e < N_EDGES) {
        int src = ei[e];
        int dst = ei[N_EDGES + e];
        if ((unsigned)dst < (unsigned)N_NODES && (unsigned)src < (unsigned)N_NODES) {
            int pos = atomicAdd(&g_cur[dst], 1);
            if ((unsigned)pos < (unsigned)N_EDGES) g_csr[pos] = src;
        }
    }
}

// ---------------- weight transpose+concat: Wcat[k][f] ----------------
__global__ void k_wcat(const float* __restrict__ Wl, const float* __restrict__ Wr,
                       int DIN, int layer) {
    float* dst = (layer == 0) ? g_W0 : (layer == 1) ? g_W1 : g_W2;
    int i = blockIdx.x * blockDim.x + threadIdx.x;
    int total = 2 * DIN * HID;
    if (i < total) {
        int k = i >> 7;
        int f = i & 127;
        dst[i] = (k < DIN) ? Wl[f * DIN + k] : Wr[f * DIN + (k - DIN)];
    }
}

// ---------------- aggregation d=64: two nodes per warp, float4 gather ----------------
__global__ void k_agg64(const float* __restrict__ x) {
    int w    = (blockIdx.x * blockDim.x + threadIdx.x) >> 5;
    int lane = threadIdx.x & 31;
    int node = w * 2 + (lane >> 4);
    int il   = lane & 15;
    if (node >= N_NODES) return;
    int start = g_off[node];
    int cnt   = g_cnt[node];
    const float4* __restrict__ x4 = (const float4*)x;
    float4 a = make_float4(0.f, 0.f, 0.f, 0.f);
    for (int e = 0; e < cnt; e++) {
        int s = g_csr[start + e];
        float4 v = x4[(size_t)s * 16 + il];
        a.x += v.x; a.y += v.y; a.z += v.z; a.w += v.w;
    }
    float inv = 1.f / fmaxf((float)cnt, 1.f);
    a.x *= inv; a.y *= inv; a.z *= inv; a.w *= inv;
    ((float4*)g_mean)[(size_t)node * 16 + il] = a;
}

// ---------------- aggregation d=128: warp per node, float4 gather ----------------
__global__ void k_agg128() {
    int gw   = (blockIdx.x * blockDim.x + threadIdx.x) >> 5;
    int lane = threadIdx.x & 31;
    if (gw >= N_NODES) return;
    int start = g_off[gw];
    int cnt   = g_cnt[gw];
    const float4* __restrict__ h4 = (const float4*)g_h;
    float4 a = make_float4(0.f, 0.f, 0.f, 0.f);
    for (int e = 0; e < cnt; e++) {
        int s = g_csr[start + e];
        float4 v = h4[(size_t)s * 32 + lane];
        a.x += v.x; a.y += v.y; a.z += v.z; a.w += v.w;
    }
    float inv = 1.f / fmaxf((float)cnt, 1.f);
    a.x *= inv; a.y *= inv; a.z *= inv; a.w *= inv;
    ((float4*)g_mean)[(size_t)gw * 32 + lane] = a;
}

// ---------------- fused transform + L2-normalize (+relu) ----------------
// out = normalize(mean@Wl^T + bias + x@Wr^T), K = 2*DIN virtual reduction.
// Block: 256 threads, tile 128 nodes x 128 f. Thread: 8 nodes x 8 cols,
// node-pair-packed f32x2 accumulators. Row norm via 16-lane shfl reduction.
#define AS_STRIDE 130
__global__ __launch_bounds__(256) void k_transform(
    const float* __restrict__ xin, int use_h, int layer,
    const float* __restrict__ bias, int DIN, int relu, int to_out,
    float* __restrict__ dout)
{
    const float* __restrict__ A1 = g_mean;
    const float* __restrict__ A2 = use_h ? g_h : xin;
    const float* __restrict__ W  = (layer == 0) ? g_W0 : (layer == 1) ? g_W1 : g_W2;

    __shared__ __align__(16) float As[32 * AS_STRIDE];  // [kk][node], stride even for LDS.64
    __shared__ __align__(16) float Ws[32 * 128];        // [kk][f]

    const int tid   = threadIdx.x;
    const int tx    = tid & 15;          // f group   (lane 0..15 within half-warp)
    const int ty    = tid >> 4;          // node group
    const int f0    = tx * 8;
    const int nl0   = ty * 8;
    const int node0 = blockIdx.x * 128;

    unsigned long long acc[4][8];        // [node pair][col]
#pragma unroll
    for (int p = 0; p < 4; p++)
#pragma unroll
        for (int j = 0; j < 8; j++) acc[p][j] = 0ull;

    const int K   = 2 * DIN;
    const int lkk = tid & 31;            // k within chunk (A loader)
    const int lng = tid >> 5;            // warp id 0..7  (A loader node group)
    const int lf  = tid & 127;           // f             (W loader)
    const int lkg = tid >> 7;            // 0..1          (W loader k group)

    for (int c0 = 0; c0 < K; c0 += 32) {
        const float* Asrc = (c0 < DIN) ? A1 : A2;
        const int cb = (c0 < DIN) ? c0 : (c0 - DIN);
#pragma unroll
        for (int r = 0; r < 16; r++) {
            int n = lng * 16 + r;
            int node = node0 + n;
            float v = (node < N_NODES) ? Asrc[(size_t)node * DIN + cb + lkk] : 0.f;
            As[lkk * AS_STRIDE + n] = v;
        }
#pragma unroll
        for (int r = 0; r < 16; r++) {
            int kk = lkg * 16 + r;
            Ws[kk * 128 + lf] = W[(size_t)(c0 + kk) * 128 + lf];
        }
        __syncthreads();

#pragma unroll
        for (int kk = 0; kk < 32; kk++) {
            const unsigned long long* ap =
                (const unsigned long long*)&As[kk * AS_STRIDE + nl0];
            unsigned long long a0 = ap[0], a1 = ap[1], a2 = ap[2], a3 = ap[3];
            float4 w0 = *(const float4*)&Ws[kk * 128 + f0];
            float4 w1 = *(const float4*)&Ws[kk * 128 + f0 + 4];
            unsigned long long wd[8] = {
                pack2(w0.x), pack2(w0.y), pack2(w0.z), pack2(w0.w),
                pack2(w1.x), pack2(w1.y), pack2(w1.z), pack2(w1.w)};
#pragma unroll
            for (int j = 0; j < 8; j++) {
                ffma2(acc[0][j], a0, wd[j]);
                ffma2(acc[1][j], a1, wd[j]);
                ffma2(acc[2][j], a2, wd[j]);
                ffma2(acc[3][j], a3, wd[j]);
            }
        }
        __syncthreads();
    }

    // ---- epilogue: bias, L2 norm over 16 tx lanes, relu, store ----
    float bs[8];
#pragma unroll
    for (int j = 0; j < 8; j++) bs[j] = bias[f0 + j];

    float vals[8][8];                    // [node 0..7][col]
#pragma unroll
    for (int p = 0; p < 4; p++)
#pragma unroll
        for (int j = 0; j < 8; j++) {
            unsigned long long v = acc[p][j];
            vals[2 * p    ][j] = __uint_as_float((unsigned)(v & 0xffffffffull)) + bs[j];
            vals[2 * p + 1][j] = __uint_as_float((unsigned)(v >> 32)) + bs[j];
        }

    float ss[8];
#pragma unroll
    for (int i = 0; i < 8; i++) {
        float s = 0.f;
#pragma unroll
        for (int j = 0; j < 8; j++) s += vals[i][j] * vals[i][j];
        ss[i] = s;
    }
#pragma unroll
    for (int m = 1; m < 16; m <<= 1)
#pragma unroll
        for (int i = 0; i < 8; i++)
            ss[i] += __shfl_xor_sync(0xffffffffu, ss[i], m);

    float* __restrict__ dest = to_out ? dout : g_h;
#pragma unroll
    for (int i = 0; i < 8; i++) {
        int node = node0 + nl0 + i;
        if (node < N_NODES) {
            float scale = 1.f / fmaxf(sqrtf(ss[i]), 1e-12f);
            float o[8];
#pragma unroll
            for (int j = 0; j < 8; j++) {
                float v = vals[i][j] * scale;
                o[j] = relu ? fmaxf(v, 0.f) : v;
            }
            *(float4*)&dest[(size_t)node * 128 + f0] =
                make_float4(o[0], o[1], o[2], o[3]);
            *(float4*)&dest[(size_t)node * 128 + f0 + 4] =
                make_float4(o[4], o[5], o[6], o[7]);
        }
    }
}

// ---------------- launch ----------------
extern "C" void kernel_launch(void* const* d_in, const int* in_sizes, int n_in,
                              void* d_out, int out_size) {
    const float* x   = (const float*)d_in[0];
    const int*   ei  = (const int*)d_in[1];     // int32 (JAX x64-disabled)
    const float* Wl0 = (const float*)d_in[2];
    const float* bl0 = (const float*)d_in[3];
    const float* Wr0 = (const float*)d_in[4];
    const float* Wl1 = (const float*)d_in[5];
    const float* bl1 = (const float*)d_in[6];
    const float* Wr1 = (const float*)d_in[7];
    const float* Wl2 = (const float*)d_in[8];
    const float* bl2 = (const float*)d_in[9];
    const float* Wr2 = (const float*)d_in[10];
    float* out = (float*)d_out;

    const int NB_NODE   = (N_NODES + 255) / 256;         // 196
    const int NB_EDGE   = (N_EDGES + 255) / 256;         // 3125
    const int NB_AGG128 = (N_NODES + 7) / 8;             // warp/node
    const int NB_AGG64  = (N_NODES / 2 + 7) / 8;         // warp / 2 nodes
    const int NB_TRANS  = (N_NODES + 127) / 128;         // 391

    // CSR build
    k_zero_cnt<<<NB_NODE, 256>>>();
    k_count<<<NB_EDGE, 256>>>(ei);
    k_scan1<<<NB_NODE, 256>>>();
    k_scan2<<<1, 256>>>(NB_NODE);
    k_scan3<<<NB_NODE, 256>>>();
    k_fill<<<NB_EDGE, 256>>>(ei);

    // weight prep
    k_wcat<<<(2 * IN_CH * HID + 255) / 256, 256>>>(Wl0, Wr0, IN_CH, 0);
    k_wcat<<<(2 * HID * HID + 255) / 256, 256>>>(Wl1, Wr1, HID, 1);
    k_wcat<<<(2 * HID * HID + 255) / 256, 256>>>(Wl2, Wr2, HID, 2);

    // layer 0: x (d=64) -> g_h (relu)
    k_agg64<<<NB_AGG64, 256>>>(x);
    k_transform<<<NB_TRANS, 256>>>(x, 0, 0, bl0, IN_CH, 1, 0, out);

    // layer 1: g_h (d=128) -> g_h (relu)
    k_agg128<<<NB_AGG128, 256>>>();
    k_transform<<<NB_TRANS, 256>>>(x, 1, 1, bl1, HID, 1, 0, out);

    // layer 2: g_h (d=128) -> out (no relu)
    k_agg128<<<NB_AGG128, 256>>>();
    k_transform<<<NB_TRANS, 256>>>(x, 1, 2, bl2, HID, 0, 1, out);
}